// round 1
// baseline (speedup 1.0000x reference)
#include <cuda_runtime.h>
#include <cuda_bf16.h>

// Problem constants (from reference)
#define NN 50000
#define KK 17
#define DIN 128
#define DOUT 64

// Scratch for projected features xp = x @ W : [N, 64] fp32 = 12.8 MB (fits in L2)
__device__ float g_xp[(size_t)NN * DOUT];

// ---------------------------------------------------------------------------
// Kernel 1: xp = x @ W   (fp32, shared-memory tiled)
// Block: 256 threads, 16 rows per block. 50000/16 = 3125 blocks exactly.
// Thread (c = tid&63, rg = (tid>>6)*4) computes rows rg..rg+3 at column c.
// ---------------------------------------------------------------------------
__global__ void __launch_bounds__(256) gemm16_kernel(
    const float* __restrict__ x, const float* __restrict__ wm)
{
    __shared__ float xs[16][DIN];    // 8 KB
    __shared__ float ws[DIN][DOUT];  // 32 KB

    const int tid = threadIdx.x;

    // Load W: 8192 floats = 2048 float4, 8 per thread
    {
        const float4* src = (const float4*)wm;
        float4* dst = (float4*)&ws[0][0];
#pragma unroll
        for (int i = 0; i < 8; i++) dst[tid + 256 * i] = src[tid + 256 * i];
    }
    // Load x tile: 16*128 floats = 512 float4, 2 per thread
    {
        const int row0 = blockIdx.x * 16;
        const float4* src = (const float4*)(x + (size_t)row0 * DIN);
        float4* dst = (float4*)&xs[0][0];
#pragma unroll
        for (int i = 0; i < 2; i++) dst[tid + 256 * i] = src[tid + 256 * i];
    }
    __syncthreads();

    const int c  = tid & 63;
    const int rg = (tid >> 6) * 4;

    float acc0 = 0.f, acc1 = 0.f, acc2 = 0.f, acc3 = 0.f;

#pragma unroll
    for (int k = 0; k < DIN; k += 4) {
        const float w0 = ws[k + 0][c];
        const float w1 = ws[k + 1][c];
        const float w2 = ws[k + 2][c];
        const float w3 = ws[k + 3][c];
        const float4 a = *(const float4*)&xs[rg + 0][k];
        const float4 b = *(const float4*)&xs[rg + 1][k];
        const float4 e = *(const float4*)&xs[rg + 2][k];
        const float4 f = *(const float4*)&xs[rg + 3][k];
        acc0 += a.x * w0 + a.y * w1 + a.z * w2 + a.w * w3;
        acc1 += b.x * w0 + b.y * w1 + b.z * w2 + b.w * w3;
        acc2 += e.x * w0 + e.y * w1 + e.z * w2 + e.w * w3;
        acc3 += f.x * w0 + f.y * w1 + f.z * w2 + f.w * w3;
    }

    const int row0 = blockIdx.x * 16;
    g_xp[(size_t)(row0 + rg + 0) * DOUT + c] = acc0;
    g_xp[(size_t)(row0 + rg + 1) * DOUT + c] = acc1;
    g_xp[(size_t)(row0 + rg + 2) * DOUT + c] = acc2;
    g_xp[(size_t)(row0 + rg + 3) * DOUT + c] = acc3;
}

// ---------------------------------------------------------------------------
// Kernel 2: weighted per-dimension median over the K=17 neighbors, then
// out[i,d] = (sum_j w_j) * median + bias[d].
//
// One thread per (node, dim). Block = 128 threads = 2 nodes.
// Median via pairwise rank accumulation:
//   s[j] = sum of weights of elements strictly before j in the stable
//          ascending sort order (value <, or value == with smaller index).
//   The reference's argmax(cumsum >= 0.5*total) picks the element with the
//   smallest s among those with s + w >= 0.5*total.
// ---------------------------------------------------------------------------
__global__ void __launch_bounds__(128) median_kernel(
    const int*   __restrict__ col,   // edge_index[1], laid out [node][K]
    const float* __restrict__ ew,    // edge_weight,    laid out [node][K]
    const float* __restrict__ bias,
    float*       __restrict__ out)
{
    __shared__ float sw[2][KK];
    __shared__ int   sc[2][KK];

    const int local = threadIdx.x >> 6;   // which node half of the block
    const int d     = threadIdx.x & 63;   // feature dim
    const int node  = blockIdx.x * 2 + local;

    if (d < KK) {
        sw[local][d] = ew[node * KK + d];
        sc[local][d] = col[node * KK + d];
    }
    __syncthreads();

    float w[KK], vals[KK];
#pragma unroll
    for (int j = 0; j < KK; j++) {
        w[j]    = sw[local][j];
        vals[j] = __ldg(&g_xp[(size_t)sc[local][j] * DOUT + d]);
    }

    float total = 0.f;
#pragma unroll
    for (int j = 0; j < KK; j++) total += w[j];
    const float hf = 0.5f * total;

    float s[KK];
#pragma unroll
    for (int j = 0; j < KK; j++) s[j] = 0.f;

    // Pairwise: exactly one of (k before j) / (j before k) holds.
    // k > j, so tie (==) means j precedes k (stable sort) -> else branch.
#pragma unroll
    for (int j = 0; j < KK; j++) {
#pragma unroll
        for (int k = j + 1; k < KK; k++) {
            if (vals[k] < vals[j]) s[j] += w[k];
            else                   s[k] += w[j];
        }
    }

    // Select element with minimal s among those whose cumulative (s+w)
    // reaches the half-total. Robust to fp: at least the max-cum element
    // always satisfies s+w >= hf.
    float bestS = 3.4e38f;
    float med   = 0.f;
#pragma unroll
    for (int j = 0; j < KK; j++) {
        if (s[j] + w[j] >= hf && s[j] < bestS) {
            bestS = s[j];
            med   = vals[j];
        }
    }

    out[(size_t)node * DOUT + d] = total * med + bias[d];
}

// ---------------------------------------------------------------------------
// Launch
// Inputs (metadata order): x[N,128] f32, edge_index[2,E] i32, edge_weight[E]
// f32, weight[128,64] f32, bias[64] f32. Output: [N,64] f32.
// ---------------------------------------------------------------------------
extern "C" void kernel_launch(void* const* d_in, const int* in_sizes, int n_in,
                              void* d_out, int out_size)
{
    const float* x    = (const float*)d_in[0];
    const int*   ei   = (const int*)  d_in[1];
    const float* ew   = (const float*)d_in[2];
    const float* wm   = (const float*)d_in[3];
    const float* bias = (const float*)d_in[4];
    float*       out  = (float*)d_out;

    const int E = in_sizes[1] / 2;         // 850000
    const int* col = ei + E;               // edge_index[1]

    gemm16_kernel<<<NN / 16, 256>>>(x, wm);
    median_kernel<<<NN / 2, 128>>>(col, ew, bias, out);
}

// round 2
// speedup vs baseline: 1.1086x; 1.1086x over previous
#include <cuda_runtime.h>
#include <cuda_bf16.h>

#define NN 50000
#define KK 17
#define DIN 128
#define DOUT 64

// Scratch for projected features xp = x @ W : [N, 64] fp32 = 12.8 MB (fits in L2)
__device__ float g_xp[(size_t)NN * DOUT];

// ---------------------------------------------------------------------------
// Kernel 1: xp = x @ W   (fp32). Tile M=128, N=64(all), K chunked by 32.
// 256 threads: thread handles 8 rows x 4 cols = 32 accumulators.
// LDS traffic ~1.5 B/FFMA -> FFMA-pipe bound (~24us floor).
// ---------------------------------------------------------------------------
__global__ void __launch_bounds__(256) gemm_kernel(
    const float* __restrict__ x, const float* __restrict__ wm)
{
    __shared__ float xs[128][32];   // 16 KB  (x tile: 128 rows x 32 k)
    __shared__ float ws[32][64];    // 8 KB   (W tile: 32 k x 64 cols)

    const int tid  = threadIdx.x;
    const int row0 = blockIdx.x * 128;
    const int c0   = (tid & 15) * 4;   // 4 output cols
    const int r0   = (tid >> 4) * 8;   // 8 output rows (within tile)

    float acc[8][4];
#pragma unroll
    for (int i = 0; i < 8; i++)
#pragma unroll
        for (int j = 0; j < 4; j++) acc[i][j] = 0.f;

    for (int k0 = 0; k0 < DIN; k0 += 32) {
        // stage x chunk: 128 rows x 32 floats = 1024 float4, 4 per thread
#pragma unroll
        for (int i = 0; i < 4; i++) {
            const int f4 = tid + 256 * i;
            const int r  = f4 >> 3;
            const int cc = (f4 & 7) * 4;
            int gr = row0 + r;
            if (gr > NN - 1) gr = NN - 1;   // clamp (stores are guarded)
            const float4 v = *(const float4*)(x + (size_t)gr * DIN + k0 + cc);
            *(float4*)&xs[r][cc] = v;
        }
        // stage W chunk: 32 x 64 floats = 512 float4, 2 per thread
#pragma unroll
        for (int i = 0; i < 2; i++) {
            const int f4 = tid + 256 * i;
            const int r  = f4 >> 4;
            const int cc = (f4 & 15) * 4;
            const float4 v = *(const float4*)(wm + (size_t)(k0 + r) * DOUT + cc);
            *(float4*)&ws[r][cc] = v;
        }
        __syncthreads();

#pragma unroll
        for (int kk = 0; kk < 32; kk += 2) {
            const float4 w0 = *(const float4*)&ws[kk][c0];
            const float4 w1 = *(const float4*)&ws[kk + 1][c0];
#pragma unroll
            for (int i = 0; i < 8; i++) {
                const float2 xv = *(const float2*)&xs[r0 + i][kk];
                acc[i][0] += xv.x * w0.x;
                acc[i][1] += xv.x * w0.y;
                acc[i][2] += xv.x * w0.z;
                acc[i][3] += xv.x * w0.w;
                acc[i][0] += xv.y * w1.x;
                acc[i][1] += xv.y * w1.y;
                acc[i][2] += xv.y * w1.z;
                acc[i][3] += xv.y * w1.w;
            }
        }
        __syncthreads();
    }

#pragma unroll
    for (int i = 0; i < 8; i++) {
        const int gr = row0 + r0 + i;
        if (gr < NN) {
            float4 v;
            v.x = acc[i][0]; v.y = acc[i][1]; v.z = acc[i][2]; v.w = acc[i][3];
            *(float4*)&g_xp[(size_t)gr * DOUT + c0] = v;
        }
    }
}

// ---------------------------------------------------------------------------
// Kernel 2: weighted per-dimension median (K=17 neighbors), then
// out[i,d] = (sum_j w_j) * median + bias[d].
// One thread per (node, dim); 256-thread blocks = 4 nodes.
// Pairwise rank accumulation with forced predicated-FADD form (3 inst/pair).
// ---------------------------------------------------------------------------
__global__ void __launch_bounds__(256) median_kernel(
    const int*   __restrict__ col,
    const float* __restrict__ ew,
    const float* __restrict__ bias,
    float*       __restrict__ out)
{
    __shared__ float swt[4][KK];
    __shared__ int   soff[4][KK];

    const int tid   = threadIdx.x;
    const int local = tid >> 6;
    const int d     = tid & 63;
    const int node  = blockIdx.x * 4 + local;

    if (d < KK) {
        swt[local][d]  = ew[node * KK + d];
        soff[local][d] = col[node * KK + d] * DOUT;   // precomputed row offset
    }
    __syncthreads();

    const float* __restrict__ xpd = g_xp + d;

    float w[KK], vals[KK];
#pragma unroll
    for (int j = 0; j < KK; j++) {
        w[j]    = swt[local][j];
        vals[j] = __ldg(xpd + soff[local][j]);
    }

    float total = 0.f;
#pragma unroll
    for (int j = 0; j < KK; j++) total += w[j];
    const float hf = 0.5f * total;

    float s[KK];
#pragma unroll
    for (int j = 0; j < KK; j++) s[j] = 0.f;

    // For each unordered pair (j<k): element k precedes j iff vals[k]<vals[j]
    // (stable ascending sort; ties -> j precedes k). Force SASS form
    // FSETP + @P FADD + @!P FADD  (1 alu + 2 fma).
#pragma unroll
    for (int j = 0; j < KK; j++) {
#pragma unroll
        for (int k = j + 1; k < KK; k++) {
            asm("{\n\t"
                ".reg .pred p;\n\t"
                "setp.lt.f32 p, %2, %3;\n\t"
                "@p  add.f32 %0, %0, %4;\n\t"
                "@!p add.f32 %1, %1, %5;\n\t"
                "}"
                : "+f"(s[j]), "+f"(s[k])
                : "f"(vals[k]), "f"(vals[j]), "f"(w[k]), "f"(w[j]));
        }
    }

    // Pick element with minimal prefix-sum s among those whose cumulative
    // (s+w) reaches the half-total (robust to fp reordering).
    float bestS = 3.4e38f;
    float med   = 0.f;
#pragma unroll
    for (int j = 0; j < KK; j++) {
        const float cum = s[j] + w[j];
        if (cum >= hf && s[j] < bestS) {
            bestS = s[j];
            med   = vals[j];
        }
    }

    out[(size_t)node * DOUT + d] = total * med + __ldg(&bias[d]);
}

// ---------------------------------------------------------------------------
// Inputs: x[N,128] f32, edge_index[2,E] i32, edge_weight[E] f32,
//         weight[128,64] f32, bias[64] f32. Output: [N,64] f32.
// ---------------------------------------------------------------------------
extern "C" void kernel_launch(void* const* d_in, const int* in_sizes, int n_in,
                              void* d_out, int out_size)
{
    const float* x    = (const float*)d_in[0];
    const int*   ei   = (const int*)  d_in[1];
    const float* ew   = (const float*)d_in[2];
    const float* wm   = (const float*)d_in[3];
    const float* bias = (const float*)d_in[4];
    float*       out  = (float*)d_out;

    const int E = in_sizes[1] / 2;
    const int* col = ei + E;

    gemm_kernel<<<(NN + 127) / 128, 256>>>(x, wm);
    median_kernel<<<NN / 4, 256>>>(col, ew, bias, out);
}